// round 15
// baseline (speedup 1.0000x reference)
#include <cuda_runtime.h>

#define NB 32768
#define NK 8192
#define ND 256
#define BETA 0.25f

#define BM 128
#define BN 128
#define BD 32
#define SLD 132                // padded row stride (528 B, 16B-aligned)

// Scratch (no allocations allowed in kernel_launch).
__device__ float g_znorm[NB];
__device__ float g_enorm[NK];
__device__ int   g_idx[NB];
__device__ float g_partial[NB];

// ---------------------------------------------------------------------------
// Row squared-norms for BOTH tensors in one launch: warp per row.
// gw < NB -> z row gw ; else e row gw-NB.
// ---------------------------------------------------------------------------
__global__ void vq_rownorm_kernel(const float* __restrict__ z, const float* __restrict__ e) {
    int gw   = (int)((blockIdx.x * (unsigned)blockDim.x + threadIdx.x) >> 5);
    int lane = threadIdx.x & 31;
    if (gw >= NB + NK) return;
    const float4* row = (gw < NB) ? (const float4*)(z + (size_t)gw * ND)
                                  : (const float4*)(e + (size_t)(gw - NB) * ND);
    float4 v0 = row[lane];
    float4 v1 = row[lane + 32];
    float s = v0.x * v0.x + v0.y * v0.y + v0.z * v0.z + v0.w * v0.w
            + v1.x * v1.x + v1.y * v1.y + v1.z * v1.z + v1.w * v1.w;
#pragma unroll
    for (int off = 16; off > 0; off >>= 1)
        s += __shfl_down_sync(0xffffffffu, s, off);
    if (lane == 0) {
        if (gw < NB) g_znorm[gw] = s;
        else         g_enorm[gw - NB] = s;
    }
}

// ---------------------------------------------------------------------------
// Fused distance-GEMM + running argmin. 8x16 register tile, 128 threads/CTA,
// 2 CTAs/SM. Per-(row,code) dot is the same sequential-fma chain (BD=32
// chunks, dd ascending) as the R2-proven kernel -> indices bit-identical.
// dist = fmaf(-2, dot, ||z||^2 + ||e||^2); ascending-k strict '<' tie-break.
// ---------------------------------------------------------------------------
__global__ __launch_bounds__(128, 2)
void vq_argmin_kernel(const float* __restrict__ z, const float* __restrict__ e) {
    __shared__ float smem[2 * BD * SLD + BN];   // zs | es | bsh (~34 KB)
    float* zs  = smem;                 // [dim][row]
    float* es  = smem + BD * SLD;      // [dim][code]
    float* bsh = smem + 2 * BD * SLD;

    const int tid = threadIdx.x;
    const int tx  = tid & 7;           // 8 positions x 16 codes
    const int ty  = tid >> 3;          // 16 positions x 8 rows
    const int m0  = blockIdx.x * BM;

    float best[8];
    int   bidx[8];
#pragma unroll
    for (int i = 0; i < 8; i++) { best[i] = 3.4028235e38f; bidx[i] = 0; }

    float arow[8];
#pragma unroll
    for (int i = 0; i < 8; i++) arow[i] = g_znorm[m0 + ty * 8 + i];

    const int lc = tid & 31;   // dim within chunk
    const int lr = tid >> 5;   // base row (0..3) for tile loads

    for (int k0 = 0; k0 < NK; k0 += BN) {
        if (tid < BN) bsh[tid] = g_enorm[k0 + tid];

        float acc[8][16];
#pragma unroll
        for (int i = 0; i < 8; i++)
#pragma unroll
            for (int j = 0; j < 16; j++) acc[i][j] = 0.0f;

        for (int d0 = 0; d0 < ND; d0 += BD) {
            __syncthreads();   // protect smem tiles (and bsh on first pass)
#pragma unroll
            for (int rr = 0; rr < BM; rr += 4) {
                zs[lc * SLD + lr + rr] = z[(size_t)(m0 + lr + rr) * ND + d0 + lc];
                es[lc * SLD + lr + rr] = e[(size_t)(k0 + lr + rr) * ND + d0 + lc];
            }
            __syncthreads();
#pragma unroll 4
            for (int dd = 0; dd < BD; dd++) {
                float4 za0 = *(const float4*)&zs[dd * SLD + ty * 8];
                float4 za1 = *(const float4*)&zs[dd * SLD + ty * 8 + 4];
                float4 eb0 = *(const float4*)&es[dd * SLD + tx * 16];
                float4 eb1 = *(const float4*)&es[dd * SLD + tx * 16 + 4];
                float4 eb2 = *(const float4*)&es[dd * SLD + tx * 16 + 8];
                float4 eb3 = *(const float4*)&es[dd * SLD + tx * 16 + 12];
                float za[8] = {za0.x, za0.y, za0.z, za0.w, za1.x, za1.y, za1.z, za1.w};
                float eb[16] = {eb0.x, eb0.y, eb0.z, eb0.w, eb1.x, eb1.y, eb1.z, eb1.w,
                                eb2.x, eb2.y, eb2.z, eb2.w, eb3.x, eb3.y, eb3.z, eb3.w};
#pragma unroll
                for (int i = 0; i < 8; i++)       // za[i] held in reuse slot
#pragma unroll
                    for (int j = 0; j < 16; j++)
                        acc[i][j] = fmaf(za[i], eb[j], acc[i][j]);
            }
        }

        // Epilogue: distances + running argmin for this code tile.
#pragma unroll
        for (int i = 0; i < 8; i++) {
#pragma unroll
            for (int j = 0; j < 16; j++) {
                float dv = fmaf(-2.0f, acc[i][j], arow[i] + bsh[tx * 16 + j]);
                int   kk = k0 + tx * 16 + j;
                if (dv < best[i]) { best[i] = dv; bidx[i] = kk; }
            }
        }
        __syncthreads();   // bsh is rewritten at top of next tile
    }

    // Cross-thread reduction: 8 threads (tx) share each of the 128 rows.
    float* rval = smem;                        // BM*8 floats
    int*   ridx = (int*)(smem + BM * 8);       // BM*8 ints
#pragma unroll
    for (int i = 0; i < 8; i++) {
        rval[(ty * 8 + i) * 8 + tx] = best[i];
        ridx[(ty * 8 + i) * 8 + tx] = bidx[i];
    }
    __syncthreads();
    if (tid < BM) {
        float bv = rval[tid * 8];
        int   bi = ridx[tid * 8];
#pragma unroll
        for (int t = 1; t < 8; t++) {
            float v  = rval[tid * 8 + t];
            int   ix = ridx[tid * 8 + t];
            if (v < bv || (v == bv && ix < bi)) { bv = v; bi = ix; }
        }
        g_idx[m0 + tid] = bi;
    }
}

// ---------------------------------------------------------------------------
// Gather + straight-through + per-row loss partial + index output.
// 4 rows per 256-thread block, float4-vectorized (64 threads per row).
// ---------------------------------------------------------------------------
__global__ void vq_gather_kernel(const float* __restrict__ z,
                                 const float* __restrict__ e,
                                 float* __restrict__ out) {
    int tid  = threadIdx.x;
    int row  = blockIdx.x * 4 + (tid >> 6);
    int seg  = tid & 63;
    int idx  = g_idx[row];

    float4 zv = *(const float4*)&z[(size_t)row * ND + seg * 4];
    float4 ev = *(const float4*)&e[(size_t)idx * ND + seg * 4];
    float4 d, o;
    d.x = ev.x - zv.x; d.y = ev.y - zv.y; d.z = ev.z - zv.z; d.w = ev.w - zv.w;
    o.x = zv.x + d.x;  o.y = zv.y + d.y;  o.z = zv.z + d.z;  o.w = zv.w + d.w;
    *(float4*)&out[(size_t)row * ND + seg * 4] = o;
    float sq = d.x * d.x + d.y * d.y + d.z * d.z + d.w * d.w;

#pragma unroll
    for (int off = 16; off > 0; off >>= 1)
        sq += __shfl_down_sync(0xffffffffu, sq, off);

    __shared__ float red[8];
    if ((tid & 31) == 0) red[tid >> 5] = sq;
    __syncthreads();
    if ((tid & 63) == 0) {
        int w = tid >> 5;
        g_partial[row] = red[w] + red[w + 1];
        out[(size_t)NB * ND + 2 + row] = (float)idx;
    }
}

// ---------------------------------------------------------------------------
// Final scalar reduction: sums per-row loss partials, writes both losses.
// ---------------------------------------------------------------------------
__global__ void vq_finalize_kernel(float* __restrict__ out) {
    int t = threadIdx.x;
    float s = 0.0f;
    for (int i = t; i < NB; i += 256) s += g_partial[i];
#pragma unroll
    for (int off = 16; off > 0; off >>= 1)
        s += __shfl_down_sync(0xffffffffu, s, off);
    __shared__ float red[8];
    if ((t & 31) == 0) red[t >> 5] = s;
    __syncthreads();
    if (t == 0) {
        float tot = 0.0f;
#pragma unroll
        for (int w = 0; w < 8; w++) tot += red[w];
        float l = BETA * (tot / (float)((size_t)NB * ND));
        out[(size_t)NB * ND]     = l;   // vq_loss
        out[(size_t)NB * ND + 1] = l;   // commit (numerically identical)
    }
}

extern "C" void kernel_launch(void* const* d_in, const int* in_sizes, int n_in,
                              void* d_out, int out_size) {
    const float* z = (const float*)d_in[0];
    const float* e = (const float*)d_in[1];
    float* out = (float*)d_out;

    vq_rownorm_kernel<<<((NB + NK) * 32 + 255) / 256, 256>>>(z, e);
    vq_argmin_kernel<<<NB / BM, 128>>>(z, e);
    vq_gather_kernel<<<NB / 4, 256>>>(z, e, out);
    vq_finalize_kernel<<<1, 256>>>(out);
}

// round 16
// speedup vs baseline: 1.5553x; 1.5553x over previous
#include <cuda_runtime.h>

#define NB 32768
#define NK 8192
#define ND 256
#define BETA 0.25f

#define BM 128
#define BN 128
#define BD 32
#define SPAD 4
#define SLD (BM + SPAD)

// Scratch (no allocations allowed in kernel_launch).
__device__ float g_znorm[NB];
__device__ float g_enorm[NK];
__device__ int   g_idx[NB];
__device__ float g_partial[NB];

// ---------------------------------------------------------------------------
// Row squared-norms for BOTH tensors in one launch: warp per row.
// gw < NB -> z row gw ; else e row gw-NB.  (R15-proven)
// ---------------------------------------------------------------------------
__global__ void vq_rownorm_kernel(const float* __restrict__ z, const float* __restrict__ e) {
    int gw   = (int)((blockIdx.x * (unsigned)blockDim.x + threadIdx.x) >> 5);
    int lane = threadIdx.x & 31;
    if (gw >= NB + NK) return;
    const float4* row = (gw < NB) ? (const float4*)(z + (size_t)gw * ND)
                                  : (const float4*)(e + (size_t)(gw - NB) * ND);
    float4 v0 = row[lane];
    float4 v1 = row[lane + 32];
    float s = v0.x * v0.x + v0.y * v0.y + v0.z * v0.z + v0.w * v0.w
            + v1.x * v1.x + v1.y * v1.y + v1.z * v1.z + v1.w * v1.w;
#pragma unroll
    for (int off = 16; off > 0; off >>= 1)
        s += __shfl_down_sync(0xffffffffu, s, off);
    if (lane == 0) {
        if (gw < NB) g_znorm[gw] = s;
        else         g_enorm[gw - NB] = s;
    }
}

// ---------------------------------------------------------------------------
// Fused distance-GEMM + running argmin — the R2 kernel verbatim (best
// measured: 3617.8 us, rel_err 1.19e-7, ~100% of effective FFMA roofline).
// 256 threads, 8x8 register tile, BM=BN=128, BD=32, 2 CTAs/SM.
// dist = fmaf(-2, dot, ||z||^2 + ||e||^2) matches the reference expression
// tree; ascending-k strict '<' + smallest-index reduce = jnp.argmin.
// ---------------------------------------------------------------------------
__global__ __launch_bounds__(256, 2)
void vq_argmin_kernel(const float* __restrict__ z, const float* __restrict__ e) {
    __shared__ float smem[2 * BD * SLD + BN];   // zs | es | bsh  (~34 KB)
    float* zs  = smem;
    float* es  = smem + BD * SLD;
    float* bsh = smem + 2 * BD * SLD;

    int tid = threadIdx.x;
    int tx  = tid & 15;   // code sub-tile (8 codes)
    int ty  = tid >> 4;   // row sub-tile  (8 rows)
    int m0  = blockIdx.x * BM;

    float best[8];
    int   bidx[8];
#pragma unroll
    for (int i = 0; i < 8; i++) { best[i] = 3.4028235e38f; bidx[i] = 0; }

    float arow[8];
#pragma unroll
    for (int i = 0; i < 8; i++) arow[i] = g_znorm[m0 + ty * 8 + i];

    const int lc = tid & 31;   // d-column within chunk
    const int lr = tid >> 5;   // base row for tile loads

    for (int k0 = 0; k0 < NK; k0 += BN) {
        if (tid < BN) bsh[tid] = g_enorm[k0 + tid];

        float acc[8][8];
#pragma unroll
        for (int i = 0; i < 8; i++)
#pragma unroll
            for (int j = 0; j < 8; j++) acc[i][j] = 0.0f;

        for (int d0 = 0; d0 < ND; d0 += BD) {
            __syncthreads();   // protect smem tiles (and bsh on first pass)
#pragma unroll
            for (int rr = 0; rr < BM; rr += 8) {
                zs[lc * SLD + lr + rr] = z[(size_t)(m0 + lr + rr) * ND + d0 + lc];
                es[lc * SLD + lr + rr] = e[(size_t)(k0 + lr + rr) * ND + d0 + lc];
            }
            __syncthreads();
#pragma unroll 8
            for (int dd = 0; dd < BD; dd++) {
                float4 za0 = *(const float4*)&zs[dd * SLD + ty * 8];
                float4 za1 = *(const float4*)&zs[dd * SLD + ty * 8 + 4];
                float4 eb0 = *(const float4*)&es[dd * SLD + tx * 8];
                float4 eb1 = *(const float4*)&es[dd * SLD + tx * 8 + 4];
                float za[8] = {za0.x, za0.y, za0.z, za0.w, za1.x, za1.y, za1.z, za1.w};
                float eb[8] = {eb0.x, eb0.y, eb0.z, eb0.w, eb1.x, eb1.y, eb1.z, eb1.w};
#pragma unroll
                for (int i = 0; i < 8; i++)
#pragma unroll
                    for (int j = 0; j < 8; j++)
                        acc[i][j] = fmaf(za[i], eb[j], acc[i][j]);
            }
        }

        // Epilogue: distances + running argmin for this code tile.
#pragma unroll
        for (int i = 0; i < 8; i++) {
#pragma unroll
            for (int j = 0; j < 8; j++) {
                float dv = fmaf(-2.0f, acc[i][j], arow[i] + bsh[tx * 8 + j]);
                int   kk = k0 + tx * 8 + j;
                if (dv < best[i]) { best[i] = dv; bidx[i] = kk; }
            }
        }
        __syncthreads();   // bsh is rewritten at top of next tile
    }

    // Cross-thread reduction: 16 threads (tx) share each of the 128 rows.
    float* rval = smem;                       // BM*16 floats
    int*   ridx = (int*)(smem + BM * 16);     // BM*16 ints
#pragma unroll
    for (int i = 0; i < 8; i++) {
        rval[(ty * 8 + i) * 16 + tx] = best[i];
        ridx[(ty * 8 + i) * 16 + tx] = bidx[i];
    }
    __syncthreads();
    if (tid < BM) {
        float bv = rval[tid * 16];
        int   bi = ridx[tid * 16];
#pragma unroll
        for (int t = 1; t < 16; t++) {
            float v  = rval[tid * 16 + t];
            int   ix = ridx[tid * 16 + t];
            if (v < bv || (v == bv && ix < bi)) { bv = v; bi = ix; }
        }
        g_idx[m0 + tid] = bi;
    }
}

// ---------------------------------------------------------------------------
// Gather + straight-through + per-row loss partial + index output.
// 4 rows per 256-thread block, float4-vectorized. (R15-proven)
// ---------------------------------------------------------------------------
__global__ void vq_gather_kernel(const float* __restrict__ z,
                                 const float* __restrict__ e,
                                 float* __restrict__ out) {
    int tid  = threadIdx.x;
    int row  = blockIdx.x * 4 + (tid >> 6);
    int seg  = tid & 63;
    int idx  = g_idx[row];

    float4 zv = *(const float4*)&z[(size_t)row * ND + seg * 4];
    float4 ev = *(const float4*)&e[(size_t)idx * ND + seg * 4];
    float4 d, o;
    d.x = ev.x - zv.x; d.y = ev.y - zv.y; d.z = ev.z - zv.z; d.w = ev.w - zv.w;
    o.x = zv.x + d.x;  o.y = zv.y + d.y;  o.z = zv.z + d.z;  o.w = zv.w + d.w;
    *(float4*)&out[(size_t)row * ND + seg * 4] = o;
    float sq = d.x * d.x + d.y * d.y + d.z * d.z + d.w * d.w;

#pragma unroll
    for (int off = 16; off > 0; off >>= 1)
        sq += __shfl_down_sync(0xffffffffu, sq, off);

    __shared__ float red[8];
    if ((tid & 31) == 0) red[tid >> 5] = sq;
    __syncthreads();
    if ((tid & 63) == 0) {
        int w = tid >> 5;
        g_partial[row] = red[w] + red[w + 1];
        out[(size_t)NB * ND + 2 + row] = (float)idx;
    }
}

// ---------------------------------------------------------------------------
// Final scalar reduction: sums per-row loss partials, writes both losses.
// ---------------------------------------------------------------------------
__global__ void vq_finalize_kernel(float* __restrict__ out) {
    int t = threadIdx.x;
    float s = 0.0f;
    for (int i = t; i < NB; i += 256) s += g_partial[i];
#pragma unroll
    for (int off = 16; off > 0; off >>= 1)
        s += __shfl_down_sync(0xffffffffu, s, off);
    __shared__ float red[8];
    if ((t & 31) == 0) red[t >> 5] = s;
    __syncthreads();
    if (t == 0) {
        float tot = 0.0f;
#pragma unroll
        for (int w = 0; w < 8; w++) tot += red[w];
        float l = BETA * (tot / (float)((size_t)NB * ND));
        out[(size_t)NB * ND]     = l;   // vq_loss
        out[(size_t)NB * ND + 1] = l;   // commit (numerically identical)
    }
}

extern "C" void kernel_launch(void* const* d_in, const int* in_sizes, int n_in,
                              void* d_out, int out_size) {
    const float* z = (const float*)d_in[0];
    const float* e = (const float*)d_in[1];
    float* out = (float*)d_out;

    vq_rownorm_kernel<<<((NB + NK) * 32 + 255) / 256, 256>>>(z, e);
    vq_argmin_kernel<<<NB / BM, 256>>>(z, e);
    vq_gather_kernel<<<NB / 4, 256>>>(z, e, out);
    vq_finalize_kernel<<<1, 256>>>(out);
}

// round 17
// speedup vs baseline: 1.7634x; 1.1338x over previous
#include <cuda_runtime.h>

#define NB 32768
#define NK 8192
#define ND 256
#define BETA 0.25f

#define BM 128
#define BN 128
#define BD 32
#define SPAD 4
#define SLD (BM + SPAD)
#define KS 4                  // k-split factor
#define KSEG (NK / KS)        // 2048 codes per split

// Scratch (no allocations allowed in kernel_launch).
__device__ float g_znorm[NB];
__device__ float g_enorm[NK];
__device__ float g_pbest[NB * KS];
__device__ int   g_pidx[NB * KS];
__device__ int   g_idx[NB];
__device__ float g_partial[NB];

// ---------------------------------------------------------------------------
// Row squared-norms for BOTH tensors in one launch: warp per row.
// ---------------------------------------------------------------------------
__global__ void vq_rownorm_kernel(const float* __restrict__ z, const float* __restrict__ e) {
    int gw   = (int)((blockIdx.x * (unsigned)blockDim.x + threadIdx.x) >> 5);
    int lane = threadIdx.x & 31;
    if (gw >= NB + NK) return;
    const float4* row = (gw < NB) ? (const float4*)(z + (size_t)gw * ND)
                                  : (const float4*)(e + (size_t)(gw - NB) * ND);
    float4 v0 = row[lane];
    float4 v1 = row[lane + 32];
    float s = v0.x * v0.x + v0.y * v0.y + v0.z * v0.z + v0.w * v0.w
            + v1.x * v1.x + v1.y * v1.y + v1.z * v1.z + v1.w * v1.w;
#pragma unroll
    for (int off = 16; off > 0; off >>= 1)
        s += __shfl_down_sync(0xffffffffu, s, off);
    if (lane == 0) {
        if (gw < NB) g_znorm[gw] = s;
        else         g_enorm[gw - NB] = s;
    }
}

// ---------------------------------------------------------------------------
// Fused distance-GEMM + running argmin over ONE k-quarter. Inner loop is the
// R2/R16 kernel verbatim (8x8 tile, 256 threads, 2 CTAs/SM); only the k range
// differs. 1024 CTAs quarter the per-CTA work so dynamic scheduling keeps all
// SMs 2-resident until the tail (makespan -> ideal). Per-(row,code) fma chain,
// dist rounding, and ascending-k strict '<' are bit-identical to R2.
// ---------------------------------------------------------------------------
__global__ __launch_bounds__(256, 2)
void vq_argmin_kernel(const float* __restrict__ z, const float* __restrict__ e) {
    __shared__ float smem[2 * BD * SLD + BN];   // zs | es | bsh  (~34 KB)
    float* zs  = smem;
    float* es  = smem + BD * SLD;
    float* bsh = smem + 2 * BD * SLD;

    int tid = threadIdx.x;
    int tx  = tid & 15;   // code sub-tile (8 codes)
    int ty  = tid >> 4;   // row sub-tile  (8 rows)
    int m0  = (blockIdx.x >> 2) * BM;           // row block
    int ks0 = (blockIdx.x & 3) * KSEG;          // code range start

    float best[8];
    int   bidx[8];
#pragma unroll
    for (int i = 0; i < 8; i++) { best[i] = 3.4028235e38f; bidx[i] = 0; }

    float arow[8];
#pragma unroll
    for (int i = 0; i < 8; i++) arow[i] = g_znorm[m0 + ty * 8 + i];

    const int lc = tid & 31;   // d-column within chunk
    const int lr = tid >> 5;   // base row for tile loads

    for (int k0 = ks0; k0 < ks0 + KSEG; k0 += BN) {
        if (tid < BN) bsh[tid] = g_enorm[k0 + tid];

        float acc[8][8];
#pragma unroll
        for (int i = 0; i < 8; i++)
#pragma unroll
            for (int j = 0; j < 8; j++) acc[i][j] = 0.0f;

        for (int d0 = 0; d0 < ND; d0 += BD) {
            __syncthreads();   // protect smem tiles (and bsh on first pass)
#pragma unroll
            for (int rr = 0; rr < BM; rr += 8) {
                zs[lc * SLD + lr + rr] = z[(size_t)(m0 + lr + rr) * ND + d0 + lc];
                es[lc * SLD + lr + rr] = e[(size_t)(k0 + lr + rr) * ND + d0 + lc];
            }
            __syncthreads();
#pragma unroll 8
            for (int dd = 0; dd < BD; dd++) {
                float4 za0 = *(const float4*)&zs[dd * SLD + ty * 8];
                float4 za1 = *(const float4*)&zs[dd * SLD + ty * 8 + 4];
                float4 eb0 = *(const float4*)&es[dd * SLD + tx * 8];
                float4 eb1 = *(const float4*)&es[dd * SLD + tx * 8 + 4];
                float za[8] = {za0.x, za0.y, za0.z, za0.w, za1.x, za1.y, za1.z, za1.w};
                float eb[8] = {eb0.x, eb0.y, eb0.z, eb0.w, eb1.x, eb1.y, eb1.z, eb1.w};
#pragma unroll
                for (int i = 0; i < 8; i++)
#pragma unroll
                    for (int j = 0; j < 8; j++)
                        acc[i][j] = fmaf(za[i], eb[j], acc[i][j]);
            }
        }

        // Epilogue: distances + running argmin for this code tile.
#pragma unroll
        for (int i = 0; i < 8; i++) {
#pragma unroll
            for (int j = 0; j < 8; j++) {
                float dv = fmaf(-2.0f, acc[i][j], arow[i] + bsh[tx * 8 + j]);
                int   kk = k0 + tx * 8 + j;
                if (dv < best[i]) { best[i] = dv; bidx[i] = kk; }
            }
        }
        __syncthreads();   // bsh is rewritten at top of next tile
    }

    // Cross-thread reduction: 16 threads (tx) share each of the 128 rows.
    float* rval = smem;                       // BM*16 floats
    int*   ridx = (int*)(smem + BM * 16);     // BM*16 ints
#pragma unroll
    for (int i = 0; i < 8; i++) {
        rval[(ty * 8 + i) * 16 + tx] = best[i];
        ridx[(ty * 8 + i) * 16 + tx] = bidx[i];
    }
    __syncthreads();
    if (tid < BM) {
        float bv = rval[tid * 16];
        int   bi = ridx[tid * 16];
#pragma unroll
        for (int t = 1; t < 16; t++) {
            float v  = rval[tid * 16 + t];
            int   ix = ridx[tid * 16 + t];
            if (v < bv || (v == bv && ix < bi)) { bv = v; bi = ix; }
        }
        g_pbest[(size_t)(m0 + tid) * KS + (blockIdx.x & 3)] = bv;
        g_pidx [(size_t)(m0 + tid) * KS + (blockIdx.x & 3)] = bi;
    }
}

// ---------------------------------------------------------------------------
// Merge k-split partials: ascending split order with strict '<' keeps the
// lowest-k winner on ties (splits cover ascending disjoint k ranges).
// ---------------------------------------------------------------------------
__global__ void vq_merge_kernel() {
    int row = blockIdx.x * 256 + threadIdx.x;
    float bv = g_pbest[(size_t)row * KS];
    int   bi = g_pidx[(size_t)row * KS];
#pragma unroll
    for (int s = 1; s < KS; s++) {
        float v  = g_pbest[(size_t)row * KS + s];
        int   ix = g_pidx[(size_t)row * KS + s];
        if (v < bv) { bv = v; bi = ix; }
    }
    g_idx[row] = bi;
}

// ---------------------------------------------------------------------------
// Gather + straight-through + per-row loss partial + index output.
// 4 rows per 256-thread block, float4-vectorized. (R15/R16-proven)
// ---------------------------------------------------------------------------
__global__ void vq_gather_kernel(const float* __restrict__ z,
                                 const float* __restrict__ e,
                                 float* __restrict__ out) {
    int tid  = threadIdx.x;
    int row  = blockIdx.x * 4 + (tid >> 6);
    int seg  = tid & 63;
    int idx  = g_idx[row];

    float4 zv = *(const float4*)&z[(size_t)row * ND + seg * 4];
    float4 ev = *(const float4*)&e[(size_t)idx * ND + seg * 4];
    float4 d, o;
    d.x = ev.x - zv.x; d.y = ev.y - zv.y; d.z = ev.z - zv.z; d.w = ev.w - zv.w;
    o.x = zv.x + d.x;  o.y = zv.y + d.y;  o.z = zv.z + d.z;  o.w = zv.w + d.w;
    *(float4*)&out[(size_t)row * ND + seg * 4] = o;
    float sq = d.x * d.x + d.y * d.y + d.z * d.z + d.w * d.w;

#pragma unroll
    for (int off = 16; off > 0; off >>= 1)
        sq += __shfl_down_sync(0xffffffffu, sq, off);

    __shared__ float red[8];
    if ((tid & 31) == 0) red[tid >> 5] = sq;
    __syncthreads();
    if ((tid & 63) == 0) {
        int w = tid >> 5;
        g_partial[row] = red[w] + red[w + 1];
        out[(size_t)NB * ND + 2 + row] = (float)idx;
    }
}

// ---------------------------------------------------------------------------
// Final scalar reduction: 1024 threads (32 serial loads each).
// ---------------------------------------------------------------------------
__global__ void vq_finalize_kernel(float* __restrict__ out) {
    int t = threadIdx.x;
    float s = 0.0f;
    for (int i = t; i < NB; i += 1024) s += g_partial[i];
#pragma unroll
    for (int off = 16; off > 0; off >>= 1)
        s += __shfl_down_sync(0xffffffffu, s, off);
    __shared__ float red[32];
    if ((t & 31) == 0) red[t >> 5] = s;
    __syncthreads();
    if (t < 32) {
        float v = red[t];
#pragma unroll
        for (int off = 16; off > 0; off >>= 1)
            v += __shfl_down_sync(0xffffffffu, v, off);
        if (t == 0) {
            float l = BETA * (v / (float)((size_t)NB * ND));
            out[(size_t)NB * ND]     = l;   // vq_loss
            out[(size_t)NB * ND + 1] = l;   // commit (numerically identical)
        }
    }
}

extern "C" void kernel_launch(void* const* d_in, const int* in_sizes, int n_in,
                              void* d_out, int out_size) {
    const float* z = (const float*)d_in[0];
    const float* e = (const float*)d_in[1];
    float* out = (float*)d_out;

    vq_rownorm_kernel<<<((NB + NK) * 32 + 255) / 256, 256>>>(z, e);
    vq_argmin_kernel<<<(NB / BM) * KS, 256>>>(z, e);
    vq_merge_kernel<<<NB / 256, 256>>>();
    vq_gather_kernel<<<NB / 4, 256>>>(z, e, out);
    vq_finalize_kernel<<<1, 1024>>>(out);
}